// round 1
// baseline (speedup 1.0000x reference)
#include <cuda_runtime.h>
#include <cstdint>
#include <math.h>

#define N_NODES 16000
#define E_EDGES 256000
#define G_GRAPHS 512
#define NNZV 512000

// ---------------- scratch (device globals; no allocations allowed) ----------
__device__ __align__(16) float g_cat1[(size_t)E_EDGES * 384]; // [xij(256) | gemb(128)]
__device__ __align__(16) float g_buf1[(size_t)E_EDGES * 256]; // xw1 -> acc1 -> er
__device__ __align__(16) float g_xw2[(size_t)E_EDGES * 128];
__device__ __align__(16) float g_sijb[(size_t)E_EDGES * 128]; // acc2 -> sij
__device__ __align__(16) float g_t4[(size_t)E_EDGES * 512];
__device__ __align__(16) float g_cat2[(size_t)E_EDGES * 256]; // [s(128) | gemb(128)]
__device__ __align__(16) float g_scb[(size_t)E_EDGES * 128];
__device__ __align__(16) float g_oute[(size_t)N_NODES * 256];
__device__ __align__(16) float g_D[E_EDGES];    // D, then Dinv in place
__device__ __align__(16) float g_Binv[N_NODES]; // Bdeg, then Binv in place
__device__ __align__(16) float g_nodew[N_NODES];
__device__ __align__(16) int g_gidx[E_EDGES];

__device__ __forceinline__ float sigmoidf_(float v) {
    return 1.0f / (1.0f + expf(-v));
}

// ---------------- zero helper ------------------------------------------------
__global__ void k_zero(float4* p, size_t n4) {
    size_t i = (size_t)blockIdx.x * blockDim.x + threadIdx.x;
    size_t stride = (size_t)gridDim.x * blockDim.x;
    float4 z = make_float4(0.f, 0.f, 0.f, 0.f);
    for (; i < n4; i += stride) p[i] = z;
}

// ---------------- node weight MLP: sigmoid(relu([x,proto]@w1+b1)@w2+b2) -----
__global__ void __launch_bounds__(128) k_nodew(
    const float* __restrict__ x, const float* __restrict__ gemb,
    const int* __restrict__ batch,
    const float* __restrict__ w1, const float* __restrict__ b1,
    const float* __restrict__ w2, const float* __restrict__ b2) {
    __shared__ float sin_[256];
    __shared__ float sred[128];
    int n = blockIdx.x;
    int t = threadIdx.x;
    sin_[t] = x[(size_t)n * 128 + t];
    int g = batch[n];
    sin_[128 + t] = gemb[(size_t)g * 128 + t];
    __syncthreads();
    float h = b1[t];
#pragma unroll 4
    for (int k = 0; k < 256; k++) h = fmaf(sin_[k], w1[k * 128 + t], h);
    h = fmaxf(h, 0.f);
    sred[t] = h * w2[t];
    __syncthreads();
    for (int s = 64; s > 0; s >>= 1) {
        if (t < s) sred[t] += sred[t + s];
        __syncthreads();
    }
    if (t == 0) g_nodew[n] = sigmoidf_(sred[0] + b2[0]);
}

// ---------------- build cat1 = [x[col], x[row], gemb[batch[col]]] + gidx ----
__global__ void __launch_bounds__(128) k_cat1(
    const float* __restrict__ x, const float* __restrict__ gemb,
    const int* __restrict__ eidx, const int* __restrict__ batch) {
    int e = blockIdx.x;
    int t = threadIdx.x;
    int c = eidx[e];
    int r = eidx[E_EDGES + e];
    int g = batch[c];
    if (t == 127) g_gidx[e] = g;
    float4* dst = (float4*)g_cat1 + (size_t)e * 96;
    if (t < 32) {
        dst[t] = ((const float4*)x)[(size_t)c * 32 + t];
    } else if (t < 64) {
        dst[t] = ((const float4*)x)[(size_t)r * 32 + (t - 32)];
    } else if (t < 96) {
        dst[t] = ((const float4*)gemb)[(size_t)g * 32 + (t - 64)];
    }
}

// ---------------- degrees: Bdeg over hcol; D[e] += node_w[hcol[hcol[i]]] ----
__global__ void k_deg(const int* __restrict__ hyper) {
    int i = blockIdx.x * blockDim.x + threadIdx.x;
    if (i >= NNZV) return;
    int e = hyper[i];         // hrow: graph-edge id in [0,E)
    int n = hyper[NNZV + i];  // hcol: hyperedge id in [0,N)
    atomicAdd(&g_Binv[n], 1.f);
    int n2 = hyper[NNZV + n];  // repo's double-index quirk: hcol[hcol[i]]
    atomicAdd(&g_D[e], g_nodew[n2]);
}

__global__ void k_inv() {
    int i = blockIdx.x * blockDim.x + threadIdx.x;
    if (i < N_NODES) {
        float b = g_Binv[i];
        g_Binv[i] = (b != 0.f) ? 1.f / b : 0.f;
    }
    if (i < E_EDGES) {
        float d = g_D[i];
        g_D[i] = (d != 0.f) ? 1.f / d : 0.f;
    }
}

// ---------------- SGEMM: C = act(A@W + bias), BM=128 BN=64 BK=16, 256 thr ---
__global__ void __launch_bounds__(256) sgemm_kernel(
    const float* __restrict__ A, int lda, const float* __restrict__ W,
    const float* __restrict__ bias, float* __restrict__ C, int ldc, int Kin,
    int Kout, int act) {
    __shared__ float As[16][128];
    __shared__ float Ws[16][64];
    const int tid = threadIdx.x;
    const int bm = blockIdx.y * 128;
    const int bn = blockIdx.x * 64;
    const int tx = tid & 15;   // col group 0..15
    const int ty = tid >> 4;   // row group 0..15
    const int arow = tid >> 2;
    const int acol = (tid & 3) * 4;
    const float* Ap0 = A + (size_t)(bm + arow) * lda + acol;
    const float* Ap1 = A + (size_t)(bm + arow + 64) * lda + acol;
    const int wrow = tid >> 4;
    const int wcol = (tid & 15) * 4;
    const float* Wp = W + (size_t)wrow * Kout + bn + wcol;

    float acc[8][4];
#pragma unroll
    for (int i = 0; i < 8; i++)
#pragma unroll
        for (int j = 0; j < 4; j++) acc[i][j] = 0.f;

    for (int k0 = 0; k0 < Kin; k0 += 16) {
        float4 a0 = *(const float4*)(Ap0 + k0);
        float4 a1 = *(const float4*)(Ap1 + k0);
        float4 wv = *(const float4*)(Wp + (size_t)k0 * Kout);
        __syncthreads();
        As[acol + 0][arow] = a0.x;
        As[acol + 1][arow] = a0.y;
        As[acol + 2][arow] = a0.z;
        As[acol + 3][arow] = a0.w;
        As[acol + 0][arow + 64] = a1.x;
        As[acol + 1][arow + 64] = a1.y;
        As[acol + 2][arow + 64] = a1.z;
        As[acol + 3][arow + 64] = a1.w;
        *(float4*)&Ws[wrow][wcol] = wv;
        __syncthreads();
#pragma unroll
        for (int kk = 0; kk < 16; kk++) {
            float4 av0 = *(const float4*)&As[kk][ty * 8];
            float4 av1 = *(const float4*)&As[kk][ty * 8 + 4];
            float4 wv2 = *(const float4*)&Ws[kk][tx * 4];
            float a[8] = {av0.x, av0.y, av0.z, av0.w,
                          av1.x, av1.y, av1.z, av1.w};
            float w[4] = {wv2.x, wv2.y, wv2.z, wv2.w};
#pragma unroll
            for (int i = 0; i < 8; i++)
#pragma unroll
                for (int j = 0; j < 4; j++)
                    acc[i][j] = fmaf(a[i], w[j], acc[i][j]);
        }
    }
    float bvals[4];
#pragma unroll
    for (int j = 0; j < 4; j++)
        bvals[j] = bias ? bias[bn + tx * 4 + j] : 0.f;
#pragma unroll
    for (int i = 0; i < 8; i++) {
        size_t row = (size_t)(bm + ty * 8 + i);
        float* crow = C + row * ldc + bn + tx * 4;
#pragma unroll
        for (int j = 0; j < 4; j++) {
            float v = acc[i][j] + bvals[j];
            if (act == 1) v = fmaxf(v, 0.f);
            crow[j] = v;
        }
    }
}

// ---------------- hypergraph scatter: out_e[hcol] += xw[hrow] ----------------
template <int FD>
__global__ void k_scat_fwd(const int* __restrict__ hyper,
                           const float* __restrict__ src,
                           float* __restrict__ dst) {
    int gi = blockIdx.x * blockDim.x + threadIdx.x;
    int i = gi >> 5, lane = gi & 31;
    if (i >= NNZV) return;
    int e = hyper[i], n = hyper[NNZV + i];
    const float* s = src + (size_t)e * FD;
    float* d = dst + (size_t)n * FD;
#pragma unroll
    for (int f = lane; f < FD; f += 32) atomicAdd(d + f, s[f]);
}

// ---------------- acc[hrow] += Binv[hcol] * out_e[hcol] ---------------------
template <int FD>
__global__ void k_scat_bwd(const int* __restrict__ hyper,
                           const float* __restrict__ oute,
                           float* __restrict__ acc) {
    int gi = blockIdx.x * blockDim.x + threadIdx.x;
    int i = gi >> 5, lane = gi & 31;
    if (i >= NNZV) return;
    int e = hyper[i], n = hyper[NNZV + i];
    float s = g_Binv[n];
    const float* src = oute + (size_t)n * FD;
    float* d = acc + (size_t)e * FD;
#pragma unroll
    for (int f = lane; f < FD; f += 32) atomicAdd(d + f, s * src[f]);
}

// ---------------- finalize: buf = sigmoid(Dinv[e]*buf + bias[f]) ------------
template <int FD>
__global__ void k_fin(float* __restrict__ buf, const float* __restrict__ bias) {
    size_t idx = (size_t)blockIdx.x * blockDim.x + threadIdx.x;
    if (idx >= (size_t)E_EDGES * FD) return;
    int e = (int)(idx / FD), f = (int)(idx % FD);
    float v = g_D[e] * buf[idx] + bias[f];  // g_D holds Dinv here
    buf[idx] = sigmoidf_(v);
}

// ---------------- mix: cat2[:, :128] = a0*xl + a1*sij; cat2[:,128:] = gemb ---
__global__ void k_mix(const float* __restrict__ gemb,
                      const float* __restrict__ attn) {
    size_t idx = (size_t)blockIdx.x * blockDim.x + threadIdx.x;
    if (idx >= (size_t)E_EDGES * 128) return;
    int e = (int)(idx >> 7), f = (int)(idx & 127);
    float a0 = attn[0], a1 = attn[1];
    size_t o = (size_t)e * 256 + f;
    float v = a0 * g_cat2[o] + a1 * g_sijb[idx];
    g_cat2[o] = v;
    g_cat2[o + 128] = gemb[(size_t)g_gidx[e] * 128 + f];
}

// ---------------- final: out[e] = sigmoid(dot(sc[e], w2) + b2) ---------------
__global__ void __launch_bounds__(256) k_out(const float* __restrict__ w2,
                                             const float* __restrict__ b2,
                                             float* __restrict__ out) {
    int gi = blockIdx.x * blockDim.x + threadIdx.x;
    int e = gi >> 5, lane = gi & 31;
    if (e >= E_EDGES) return;
    const float* s = g_scb + (size_t)e * 128;
    float v = 0.f;
#pragma unroll
    for (int q = 0; q < 4; q++) v = fmaf(s[lane + 32 * q], w2[lane + 32 * q], v);
#pragma unroll
    for (int off = 16; off; off >>= 1) v += __shfl_down_sync(0xffffffffu, v, off);
    if (lane == 0) out[e] = sigmoidf_(v + b2[0]);
}

// ============================================================================
extern "C" void kernel_launch(void* const* d_in, const int* in_sizes, int n_in,
                              void* d_out, int out_size) {
    const float* x = (const float*)d_in[0];
    const float* gemb = (const float*)d_in[1];
    const int* eidx = (const int*)d_in[2];
    // d_in[3] edge_type unused by reference
    const int* batch = (const int*)d_in[4];
    const int* hyper = (const int*)d_in[5];
    const float* hw_w1 = (const float*)d_in[6];
    const float* hw_b1 = (const float*)d_in[7];
    const float* hw_w2 = (const float*)d_in[8];
    const float* hw_b2 = (const float*)d_in[9];
    const float* c1_w = (const float*)d_in[10];
    const float* c1_b = (const float*)d_in[11];
    const float* c2_w = (const float*)d_in[12];
    const float* c2_b = (const float*)d_in[13];
    const float* gw1 = (const float*)d_in[14];
    const float* gb1 = (const float*)d_in[15];
    const float* gw2 = (const float*)d_in[16];
    const float* gb2 = (const float*)d_in[17];
    const float* cl_w1 = (const float*)d_in[18];
    const float* cl_b1 = (const float*)d_in[19];
    const float* cl_w2 = (const float*)d_in[20];
    const float* cl_b2 = (const float*)d_in[21];
    const float* attn = (const float*)d_in[22];
    float* out = (float*)d_out;

    float *cat1, *buf1, *xw2, *sij, *t4, *cat2, *sc, *oute, *Dp, *Binvp;
    cudaGetSymbolAddress((void**)&cat1, g_cat1);
    cudaGetSymbolAddress((void**)&buf1, g_buf1);
    cudaGetSymbolAddress((void**)&xw2, g_xw2);
    cudaGetSymbolAddress((void**)&sij, g_sijb);
    cudaGetSymbolAddress((void**)&t4, g_t4);
    cudaGetSymbolAddress((void**)&cat2, g_cat2);
    cudaGetSymbolAddress((void**)&sc, g_scb);
    cudaGetSymbolAddress((void**)&oute, g_oute);
    cudaGetSymbolAddress((void**)&Dp, g_D);
    cudaGetSymbolAddress((void**)&Binvp, g_Binv);

    const int scat_blocks = (NNZV * 32 + 255) / 256;

    // node weights + cat1 + degrees
    k_nodew<<<N_NODES, 128>>>(x, gemb, batch, hw_w1, hw_b1, hw_w2, hw_b2);
    k_cat1<<<E_EDGES, 128>>>(x, gemb, eidx, batch);
    k_zero<<<256, 256>>>((float4*)Dp, E_EDGES / 4);
    k_zero<<<64, 256>>>((float4*)Binvp, N_NODES / 4);
    k_deg<<<(NNZV + 255) / 256, 256>>>(hyper);
    k_inv<<<(E_EDGES + 255) / 256, 256>>>();

    // hconv1: xw1 = xij0 @ c1_w (Kin=256, use first 256 cols of cat1)
    {
        dim3 g(256 / 64, E_EDGES / 128);
        sgemm_kernel<<<g, 256>>>(cat1, 384, c1_w, nullptr, buf1, 256, 256, 256, 0);
    }
    k_zero<<<2048, 256>>>((float4*)oute, (size_t)N_NODES * 256 / 4);
    k_scat_fwd<256><<<scat_blocks, 256>>>(hyper, buf1, oute);
    k_zero<<<8192, 256>>>((float4*)buf1, (size_t)E_EDGES * 256 / 4);
    k_scat_bwd<256><<<scat_blocks, 256>>>(hyper, oute, buf1);
    k_fin<256><<<(int)(((size_t)E_EDGES * 256 + 255) / 256), 256>>>(buf1, c1_b);  // er

    // hconv2: xw2 = er @ c2_w
    {
        dim3 g(128 / 64, E_EDGES / 128);
        sgemm_kernel<<<g, 256>>>(buf1, 256, c2_w, nullptr, xw2, 128, 256, 128, 0);
    }
    k_zero<<<1024, 256>>>((float4*)oute, (size_t)N_NODES * 128 / 4);
    k_scat_fwd<128><<<scat_blocks, 256>>>(hyper, xw2, oute);
    k_zero<<<8192, 256>>>((float4*)sij, (size_t)E_EDGES * 128 / 4);
    k_scat_bwd<128><<<scat_blocks, 256>>>(hyper, oute, sij);
    k_fin<128><<<(int)(((size_t)E_EDGES * 128 + 255) / 256), 256>>>(sij, c2_b);

    // generator MLP
    {
        dim3 g(512 / 64, E_EDGES / 128);
        sgemm_kernel<<<g, 256>>>(cat1, 384, gw1, gb1, t4, 512, 384, 512, 1);
    }
    {
        dim3 g(128 / 64, E_EDGES / 128);
        sgemm_kernel<<<g, 256>>>(t4, 512, gw2, gb2, cat2, 256, 512, 128, 1);
    }
    k_mix<<<(int)(((size_t)E_EDGES * 128 + 255) / 256), 256>>>(gemb, attn);

    // classifier
    {
        dim3 g(128 / 64, E_EDGES / 128);
        sgemm_kernel<<<g, 256>>>(cat2, 256, cl_w1, cl_b1, sc, 128, 256, 128, 1);
    }
    k_out<<<(E_EDGES * 32 + 255) / 256, 256>>>(cl_w2, cl_b2, out);
}

// round 3
// speedup vs baseline: 1.9982x; 1.9982x over previous
#include <cuda_runtime.h>
#include <cuda_bf16.h>
#include <cstdint>
#include <math.h>

#define N_NODES 16000
#define E_EDGES 256000
#define G_GRAPHS 512
#define NNZV 512000

// ---------------- scratch (device globals; no allocations allowed) ----------
__device__ __align__(16) __nv_bfloat16 g_cat1h[(size_t)E_EDGES * 384];
__device__ __align__(16) __nv_bfloat16 g_cat1l[(size_t)E_EDGES * 384];
__device__ __align__(16) float g_buf1[(size_t)E_EDGES * 256]; // xw1 -> acc1
__device__ __align__(16) __nv_bfloat16 g_erh[(size_t)E_EDGES * 256];
__device__ __align__(16) __nv_bfloat16 g_erl[(size_t)E_EDGES * 256];
__device__ __align__(16) float g_xw2[(size_t)E_EDGES * 128];
__device__ __align__(16) float g_sijb[(size_t)E_EDGES * 128];
__device__ __align__(16) __nv_bfloat16 g_t4h[(size_t)E_EDGES * 512];
__device__ __align__(16) __nv_bfloat16 g_t4l[(size_t)E_EDGES * 512];
__device__ __align__(16) float g_xl[(size_t)E_EDGES * 128];
__device__ __align__(16) __nv_bfloat16 g_cat2h[(size_t)E_EDGES * 256];
__device__ __align__(16) __nv_bfloat16 g_cat2l[(size_t)E_EDGES * 256];
__device__ __align__(16) float g_scb[(size_t)E_EDGES * 128];
__device__ __align__(16) float g_oute[(size_t)N_NODES * 256];
__device__ __align__(16) float g_D[E_EDGES];    // D, then Dinv in place
__device__ __align__(16) float g_Binv[N_NODES]; // Bdeg, then Binv in place
__device__ __align__(16) float g_nodew[N_NODES];
__device__ __align__(16) int g_gidx[E_EDGES];
// transposed+split weights, packed: c1(256x256)@0, c2(128x256)@65536,
// g1(512x384)@98304, g2(128x512)@294912, cl1(128x256)@360448
__device__ __align__(16) __nv_bfloat16 g_wth[393216];
__device__ __align__(16) __nv_bfloat16 g_wtl[393216];

#define OFF_C1 0
#define OFF_C2 65536
#define OFF_G1 98304
#define OFF_G2 294912
#define OFF_CL 360448

__device__ __forceinline__ float sigmoidf_(float v) {
    return 1.0f / (1.0f + expf(-v));
}

__device__ __forceinline__ void bfsplit(float v, __nv_bfloat16& h, __nv_bfloat16& l) {
    h = __float2bfloat16(v);
    l = __float2bfloat16(v - __bfloat162float(h));
}

// ---------------- ptx helpers (baseline ISA only; no 'a'-gated instrs) ------
__device__ __forceinline__ uint32_t smem_u32(const void* p) {
    uint32_t a;
    asm("{ .reg .u64 t; cvta.to.shared.u64 t, %1; cvt.u32.u64 %0, t; }"
        : "=r"(a) : "l"(p));
    return a;
}
__device__ __forceinline__ void cp16(uint32_t dst, const void* src) {
    asm volatile("cp.async.cg.shared.global [%0], [%1], 16;"
                 :: "r"(dst), "l"(src) : "memory");
}
__device__ __forceinline__ void ldsm4(uint32_t* r, uint32_t addr) {
    asm volatile("ldmatrix.sync.aligned.m8n8.x4.shared.b16 {%0,%1,%2,%3}, [%4];"
                 : "=r"(r[0]), "=r"(r[1]), "=r"(r[2]), "=r"(r[3]) : "r"(addr));
}
__device__ __forceinline__ void mma16816(float* d, const uint32_t* a,
                                         const uint32_t* b) {
    asm volatile(
        "mma.sync.aligned.m16n8k16.row.col.f32.bf16.bf16.f32 "
        "{%0,%1,%2,%3}, {%4,%5,%6,%7}, {%8,%9}, {%0,%1,%2,%3};"
        : "+f"(d[0]), "+f"(d[1]), "+f"(d[2]), "+f"(d[3])
        : "r"(a[0]), "r"(a[1]), "r"(a[2]), "r"(a[3]), "r"(b[0]), "r"(b[1]));
}

// ---------------- zero helper ------------------------------------------------
__global__ void k_zero(float4* p, size_t n4) {
    size_t i = (size_t)blockIdx.x * blockDim.x + threadIdx.x;
    size_t stride = (size_t)gridDim.x * blockDim.x;
    float4 z = make_float4(0.f, 0.f, 0.f, 0.f);
    for (; i < n4; i += stride) p[i] = z;
}

// ---------------- weight transpose + bf16 split: WT[n,k] = W[k,n] -----------
__global__ void k_wt(const float* __restrict__ W, int Kin, int Kout,
                     __nv_bfloat16* __restrict__ th, __nv_bfloat16* __restrict__ tl) {
    int idx = blockIdx.x * blockDim.x + threadIdx.x;
    if (idx >= Kin * Kout) return;
    int n = idx / Kin, k = idx - n * Kin;
    float v = W[(size_t)k * Kout + n];
    __nv_bfloat16 h, l;
    bfsplit(v, h, l);
    th[idx] = h;
    tl[idx] = l;
}

// ---------------- node weight MLP --------------------------------------------
__global__ void __launch_bounds__(128) k_nodew(
    const float* __restrict__ x, const float* __restrict__ gemb,
    const int* __restrict__ batch,
    const float* __restrict__ w1, const float* __restrict__ b1,
    const float* __restrict__ w2, const float* __restrict__ b2) {
    __shared__ float sin_[256];
    __shared__ float sred[128];
    int n = blockIdx.x;
    int t = threadIdx.x;
    sin_[t] = x[(size_t)n * 128 + t];
    int g = batch[n];
    sin_[128 + t] = gemb[(size_t)g * 128 + t];
    __syncthreads();
    float h = b1[t];
#pragma unroll 4
    for (int k = 0; k < 256; k++) h = fmaf(sin_[k], w1[k * 128 + t], h);
    h = fmaxf(h, 0.f);
    sred[t] = h * w2[t];
    __syncthreads();
    for (int s = 64; s > 0; s >>= 1) {
        if (t < s) sred[t] += sred[t + s];
        __syncthreads();
    }
    if (t == 0) g_nodew[n] = sigmoidf_(sred[0] + b2[0]);
}

// ---------------- build cat1 (bf16 hi/lo) = [x[col], x[row], gemb[batch[col]]]
__global__ void __launch_bounds__(128) k_cat1(
    const float* __restrict__ x, const float* __restrict__ gemb,
    const int* __restrict__ eidx, const int* __restrict__ batch) {
    int e = blockIdx.x;
    int t = threadIdx.x;
    int c = eidx[e];
    int r = eidx[E_EDGES + e];
    int g = batch[c];
    if (t == 127) g_gidx[e] = g;
    float a = x[(size_t)c * 128 + t];
    float b = x[(size_t)r * 128 + t];
    float gv = gemb[(size_t)g * 128 + t];
    size_t base = (size_t)e * 384;
    __nv_bfloat16 h, l;
    bfsplit(a, h, l);
    g_cat1h[base + t] = h; g_cat1l[base + t] = l;
    bfsplit(b, h, l);
    g_cat1h[base + 128 + t] = h; g_cat1l[base + 128 + t] = l;
    bfsplit(gv, h, l);
    g_cat1h[base + 256 + t] = h; g_cat1l[base + 256 + t] = l;
}

// ---------------- degrees ----------------------------------------------------
__global__ void k_deg(const int* __restrict__ hyper) {
    int i = blockIdx.x * blockDim.x + threadIdx.x;
    if (i >= NNZV) return;
    int e = hyper[i];
    int n = hyper[NNZV + i];
    atomicAdd(&g_Binv[n], 1.f);
    int n2 = hyper[NNZV + n];  // repo's double-index quirk
    atomicAdd(&g_D[e], g_nodew[n2]);
}

__global__ void k_inv() {
    int i = blockIdx.x * blockDim.x + threadIdx.x;
    if (i < N_NODES) {
        float b = g_Binv[i];
        g_Binv[i] = (b != 0.f) ? 1.f / b : 0.f;
    }
    if (i < E_EDGES) {
        float d = g_D[i];
        g_D[i] = (d != 0.f) ? 1.f / d : 0.f;
    }
}

// ---------------- mma.sync bf16x3 GEMM: C = act(A@W^T' + bias) ---------------
// A hi/lo: [E, lda] bf16; WT hi/lo: [Kout, Kin] bf16 (pre-transposed weight)
// BM=128, BN=128, BK=64 bf16; 256 thr (8 warps, warp tile 32x64), dbl-buffered.
// mode 0: fp32 out (opt act/bias). mode 1: bf16 hi/lo out (bias+relu).
#define MMA_SMEM_DYN (2 * 65536)
__global__ void __launch_bounds__(256) mma_gemm(
    const __nv_bfloat16* __restrict__ Ah, const __nv_bfloat16* __restrict__ Al,
    int lda, int Kin,
    const __nv_bfloat16* __restrict__ Wh, const __nv_bfloat16* __restrict__ Wl,
    const float* __restrict__ bias,
    float* __restrict__ Cf, __nv_bfloat16* __restrict__ Ch,
    __nv_bfloat16* __restrict__ Cl, int ldc, int act, int mode) {
    extern __shared__ __align__(1024) char dynsmem[];
    const uint32_t sb = smem_u32(dynsmem);

    const int tid = threadIdx.x, wid = tid >> 5, lane = tid & 31;
    const int bm = blockIdx.y * 128, bn = blockIdx.x * 128;
    const int wm = wid & 3, wn = wid >> 2;
    const int nchunk = Kin >> 6;

    float acc[2][8][4];
#pragma unroll
    for (int s = 0; s < 2; s++)
#pragma unroll
        for (int j = 0; j < 8; j++)
#pragma unroll
            for (int q = 0; q < 4; q++) acc[s][j][q] = 0.f;

    // tile loader: 128 rows x 64 bf16 (128B rows) with SW128 chunk-xor swizzle
    auto load_tile = [&](uint32_t dst, const __nv_bfloat16* g, int ld,
                         int rowbase, int k0) {
#pragma unroll
        for (int s = 0; s < 4; s++) {
            int idx = tid + s * 256;
            int row = idx >> 3, c = idx & 7;
            uint32_t off = (uint32_t)((row << 7) + ((c << 4) ^ ((row & 7) << 4)));
            cp16(dst + off, g + (size_t)(rowbase + row) * ld + k0 + (c << 3));
        }
    };
    auto load_chunk = [&](int slot, int c) {
        uint32_t s0 = sb + slot * 65536;
        int k0 = c << 6;
        load_tile(s0 + 0,     Ah, lda, bm, k0);
        load_tile(s0 + 16384, Al, lda, bm, k0);
        load_tile(s0 + 32768, Wh, Kin, bn, k0);
        load_tile(s0 + 49152, Wl, Kin, bn, k0);
        asm volatile("cp.async.commit_group;" ::: "memory");
    };

    // per-thread ldmatrix row/col components
    const int rowA = wm * 32 + (lane & 15);
    const int k8a = (lane & 16) ? 8 : 0;
    const int rowB = wn * 64 + (lane & 7) + ((lane & 16) ? 8 : 0);
    const int k8b = (lane & 8) ? 8 : 0;

    auto compute_chunk = [&](int slot) {
        uint32_t s0 = sb + slot * 65536;
#pragma unroll
        for (int kk = 0; kk < 4; kk++) {
            uint32_t aH[2][4], aL[2][4], bH[4][4], bL[4][4];
#pragma unroll
            for (int s = 0; s < 2; s++) {
                int r = rowA + s * 16;
                uint32_t off = (uint32_t)((r << 7) +
                    (((kk * 16 + k8a) << 1) ^ ((r & 7) << 4)));
                ldsm4(aH[s], s0 + off);
                ldsm4(aL[s], s0 + 16384 + off);
            }
#pragma unroll
            for (int jp = 0; jp < 4; jp++) {
                int r = rowB + jp * 16;
                uint32_t off = (uint32_t)((r << 7) +
                    (((kk * 16 + k8b) << 1) ^ ((r & 7) << 4)));
                ldsm4(bH[jp], s0 + 32768 + off);
                ldsm4(bL[jp], s0 + 49152 + off);
            }
#pragma unroll
            for (int s = 0; s < 2; s++)
#pragma unroll
                for (int j = 0; j < 8; j++) {
                    const uint32_t* bh = &bH[j >> 1][(j & 1) * 2];
                    const uint32_t* bl = &bL[j >> 1][(j & 1) * 2];
                    mma16816(acc[s][j], aH[s], bh);
                    mma16816(acc[s][j], aL[s], bh);
                    mma16816(acc[s][j], aH[s], bl);
                }
        }
    };

    load_chunk(0, 0);
    if (nchunk > 1) load_chunk(1, 1);

    for (int c = 0; c < nchunk; c++) {
        if (c == nchunk - 1)
            asm volatile("cp.async.wait_group 0;" ::: "memory");
        else
            asm volatile("cp.async.wait_group 1;" ::: "memory");
        __syncthreads();
        compute_chunk(c & 1);
        __syncthreads();
        if (c + 2 < nchunk) load_chunk(c & 1, c + 2);
    }

    // epilogue
    const int gID = lane >> 2, tid4 = lane & 3;
#pragma unroll
    for (int s = 0; s < 2; s++) {
        int row0 = bm + wm * 32 + s * 16 + gID;
#pragma unroll
        for (int j = 0; j < 8; j++) {
            int col = bn + wn * 64 + j * 8 + tid4 * 2;
            float b0 = bias ? bias[col] : 0.f;
            float b1 = bias ? bias[col + 1] : 0.f;
            float f0 = acc[s][j][0] + b0, f1 = acc[s][j][1] + b1;
            float f2 = acc[s][j][2] + b0, f3 = acc[s][j][3] + b1;
            if (act) {
                f0 = fmaxf(f0, 0.f); f1 = fmaxf(f1, 0.f);
                f2 = fmaxf(f2, 0.f); f3 = fmaxf(f3, 0.f);
            }
            if (mode == 0) {
                *(float2*)(Cf + (size_t)row0 * ldc + col) = make_float2(f0, f1);
                *(float2*)(Cf + (size_t)(row0 + 8) * ldc + col) = make_float2(f2, f3);
            } else {
                __nv_bfloat16 h0, l0, h1, l1;
                bfsplit(f0, h0, l0); bfsplit(f1, h1, l1);
                *(__nv_bfloat162*)(Ch + (size_t)row0 * ldc + col) =
                    __halves2bfloat162(h0, h1);
                *(__nv_bfloat162*)(Cl + (size_t)row0 * ldc + col) =
                    __halves2bfloat162(l0, l1);
                bfsplit(f2, h0, l0); bfsplit(f3, h1, l1);
                *(__nv_bfloat162*)(Ch + (size_t)(row0 + 8) * ldc + col) =
                    __halves2bfloat162(h0, h1);
                *(__nv_bfloat162*)(Cl + (size_t)(row0 + 8) * ldc + col) =
                    __halves2bfloat162(l0, l1);
            }
        }
    }
}

// ---------------- hypergraph scatter: out_e[hcol] += xw[hrow] ----------------
template <int FD>
__global__ void k_scat_fwd(const int* __restrict__ hyper,
                           const float* __restrict__ src,
                           float* __restrict__ dst) {
    int gi = blockIdx.x * blockDim.x + threadIdx.x;
    int i = gi >> 5, lane = gi & 31;
    if (i >= NNZV) return;
    int e = hyper[i], n = hyper[NNZV + i];
    const float4* s = (const float4*)(src + (size_t)e * FD);
    float4* d = (float4*)(dst + (size_t)n * FD);
#pragma unroll
    for (int f = lane; f < FD / 4; f += 32) atomicAdd(d + f, s[f]);
}

// ---------------- acc[hrow] += Binv[hcol] * out_e[hcol] ---------------------
template <int FD>
__global__ void k_scat_bwd(const int* __restrict__ hyper,
                           const float* __restrict__ oute,
                           float* __restrict__ acc) {
    int gi = blockIdx.x * blockDim.x + threadIdx.x;
    int i = gi >> 5, lane = gi & 31;
    if (i >= NNZV) return;
    int e = hyper[i], n = hyper[NNZV + i];
    float sc = g_Binv[n];
    const float4* s = (const float4*)(oute + (size_t)n * FD);
    float4* d = (float4*)(acc + (size_t)e * FD);
#pragma unroll
    for (int f = lane; f < FD / 4; f += 32) {
        float4 v = s[f];
        v.x *= sc; v.y *= sc; v.z *= sc; v.w *= sc;
        atomicAdd(d + f, v);
    }
}

// ---------------- finalize hconv1 -> er bf16 hi/lo ---------------------------
__global__ void k_finbf(const float* __restrict__ acc,
                        const float* __restrict__ bias,
                        __nv_bfloat16* __restrict__ oh,
                        __nv_bfloat16* __restrict__ ol) {
    size_t idx = (size_t)blockIdx.x * blockDim.x + threadIdx.x;
    if (idx >= (size_t)E_EDGES * 256) return;
    int e = (int)(idx >> 8), f = (int)(idx & 255);
    float v = sigmoidf_(g_D[e] * acc[idx] + bias[f]);
    __nv_bfloat16 h, l;
    bfsplit(v, h, l);
    oh[idx] = h; ol[idx] = l;
}

// ---------------- finalize hconv2 (fp32 in-place, FD=128) --------------------
__global__ void k_fin128(float* __restrict__ buf, const float* __restrict__ bias) {
    size_t idx = (size_t)blockIdx.x * blockDim.x + threadIdx.x;
    if (idx >= (size_t)E_EDGES * 128) return;
    int e = (int)(idx >> 7), f = (int)(idx & 127);
    buf[idx] = sigmoidf_(g_D[e] * buf[idx] + bias[f]);
}

// ---------------- mix: cat2 = [a0*xl + a1*sij | gemb] as bf16 hi/lo ----------
__global__ void k_mix(const float* __restrict__ gemb,
                      const float* __restrict__ attn) {
    size_t idx = (size_t)blockIdx.x * blockDim.x + threadIdx.x;
    if (idx >= (size_t)E_EDGES * 128) return;
    int e = (int)(idx >> 7), f = (int)(idx & 127);
    float a0 = attn[0], a1 = attn[1];
    float v = a0 * g_xl[idx] + a1 * g_sijb[idx];
    size_t o = (size_t)e * 256 + f;
    __nv_bfloat16 h, l;
    bfsplit(v, h, l);
    g_cat2h[o] = h; g_cat2l[o] = l;
    float gv = gemb[(size_t)g_gidx[e] * 128 + f];
    bfsplit(gv, h, l);
    g_cat2h[o + 128] = h; g_cat2l[o + 128] = l;
}

// ---------------- final: out[e] = sigmoid(dot(sc[e], w2) + b2) ---------------
__global__ void __launch_bounds__(256) k_out(const float* __restrict__ w2,
                                             const float* __restrict__ b2,
                                             float* __restrict__ out) {
    int gi = blockIdx.x * blockDim.x + threadIdx.x;
    int e = gi >> 5, lane = gi & 31;
    if (e >= E_EDGES) return;
    const float* s = g_scb + (size_t)e * 128;
    float v = 0.f;
#pragma unroll
    for (int q = 0; q < 4; q++) v = fmaf(s[lane + 32 * q], w2[lane + 32 * q], v);
#pragma unroll
    for (int off = 16; off; off >>= 1) v += __shfl_down_sync(0xffffffffu, v, off);
    if (lane == 0) out[e] = sigmoidf_(v + b2[0]);
}

// ============================================================================
extern "C" void kernel_launch(void* const* d_in, const int* in_sizes, int n_in,
                              void* d_out, int out_size) {
    const float* x = (const float*)d_in[0];
    const float* gemb = (const float*)d_in[1];
    const int* eidx = (const int*)d_in[2];
    const int* batch = (const int*)d_in[4];
    const int* hyper = (const int*)d_in[5];
    const float* hw_w1 = (const float*)d_in[6];
    const float* hw_b1 = (const float*)d_in[7];
    const float* hw_w2 = (const float*)d_in[8];
    const float* hw_b2 = (const float*)d_in[9];
    const float* c1_w = (const float*)d_in[10];
    const float* c1_b = (const float*)d_in[11];
    const float* c2_w = (const float*)d_in[12];
    const float* c2_b = (const float*)d_in[13];
    const float* gw1 = (const float*)d_in[14];
    const float* gb1 = (const float*)d_in[15];
    const float* gw2 = (const float*)d_in[16];
    const float* gb2 = (const float*)d_in[17];
    const float* cl_w1 = (const float*)d_in[18];
    const float* cl_b1 = (const float*)d_in[19];
    const float* cl_w2 = (const float*)d_in[20];
    const float* cl_b2 = (const float*)d_in[21];
    const float* attn = (const float*)d_in[22];
    float* out = (float*)d_out;

    __nv_bfloat16 *cat1h, *cat1l, *erh, *erl, *t4h, *t4l, *cat2h, *cat2l, *wth, *wtl;
    float *buf1, *xw2, *sij, *xl, *sc, *oute, *Dp, *Binvp;
    cudaGetSymbolAddress((void**)&cat1h, g_cat1h);
    cudaGetSymbolAddress((void**)&cat1l, g_cat1l);
    cudaGetSymbolAddress((void**)&erh, g_erh);
    cudaGetSymbolAddress((void**)&erl, g_erl);
    cudaGetSymbolAddress((void**)&t4h, g_t4h);
    cudaGetSymbolAddress((void**)&t4l, g_t4l);
    cudaGetSymbolAddress((void**)&cat2h, g_cat2h);
    cudaGetSymbolAddress((void**)&cat2l, g_cat2l);
    cudaGetSymbolAddress((void**)&wth, g_wth);
    cudaGetSymbolAddress((void**)&wtl, g_wtl);
    cudaGetSymbolAddress((void**)&buf1, g_buf1);
    cudaGetSymbolAddress((void**)&xw2, g_xw2);
    cudaGetSymbolAddress((void**)&sij, g_sijb);
    cudaGetSymbolAddress((void**)&xl, g_xl);
    cudaGetSymbolAddress((void**)&sc, g_scb);
    cudaGetSymbolAddress((void**)&oute, g_oute);
    cudaGetSymbolAddress((void**)&Dp, g_D);
    cudaGetSymbolAddress((void**)&Binvp, g_Binv);

    cudaFuncSetAttribute(mma_gemm, cudaFuncAttributeMaxDynamicSharedMemorySize,
                         MMA_SMEM_DYN);

    const int scat_blocks = (NNZV * 32 + 255) / 256;

    // weight prep (transpose + bf16 split)
    k_wt<<<(256 * 256 + 255) / 256, 256>>>(c1_w, 256, 256, wth + OFF_C1, wtl + OFF_C1);
    k_wt<<<(128 * 256 + 255) / 256, 256>>>(c2_w, 256, 128, wth + OFF_C2, wtl + OFF_C2);
    k_wt<<<(512 * 384 + 255) / 256, 256>>>(gw1, 384, 512, wth + OFF_G1, wtl + OFF_G1);
    k_wt<<<(128 * 512 + 255) / 256, 256>>>(gw2, 512, 128, wth + OFF_G2, wtl + OFF_G2);
    k_wt<<<(128 * 256 + 255) / 256, 256>>>(cl_w1, 256, 128, wth + OFF_CL, wtl + OFF_CL);

    // node weights + cat1 + degrees
    k_nodew<<<N_NODES, 128>>>(x, gemb, batch, hw_w1, hw_b1, hw_w2, hw_b2);
    k_cat1<<<E_EDGES, 128>>>(x, gemb, eidx, batch);
    k_zero<<<256, 256>>>((float4*)Dp, E_EDGES / 4);
    k_zero<<<64, 256>>>((float4*)Binvp, N_NODES / 4);
    k_deg<<<(NNZV + 255) / 256, 256>>>(hyper);
    k_inv<<<(E_EDGES + 255) / 256, 256>>>();

    // hconv1: xw1 = xij0 @ c1_w  (Kin=256 of cat1, lda=384)
    mma_gemm<<<dim3(2, E_EDGES / 128), 256, MMA_SMEM_DYN>>>(
        cat1h, cat1l, 384, 256, wth + OFF_C1, wtl + OFF_C1, nullptr,
        buf1, nullptr, nullptr, 256, 0, 0);
    k_zero<<<2048, 256>>>((float4*)oute, (size_t)N_NODES * 256 / 4);
    k_scat_fwd<256><<<scat_blocks, 256>>>(hyper, buf1, oute);
    k_zero<<<8192, 256>>>((float4*)buf1, (size_t)E_EDGES * 256 / 4);
    k_scat_bwd<256><<<scat_blocks, 256>>>(hyper, oute, buf1);
    k_finbf<<<(int)(((size_t)E_EDGES * 256 + 255) / 256), 256>>>(buf1, c1_b, erh, erl);

    // hconv2: xw2 = er @ c2_w
    mma_gemm<<<dim3(1, E_EDGES / 128), 256, MMA_SMEM_DYN>>>(
        erh, erl, 256, 256, wth + OFF_C2, wtl + OFF_C2, nullptr,
        xw2, nullptr, nullptr, 128, 0, 0);
    k_zero<<<1024, 256>>>((float4*)oute, (size_t)N_NODES * 128 / 4);
    k_scat_fwd<128><<<scat_blocks, 256>>>(hyper, xw2, oute);
    k_zero<<<8192, 256>>>((float4*)sij, (size_t)E_EDGES * 128 / 4);
    k_scat_bwd<128><<<scat_blocks, 256>>>(hyper, oute, sij);
    k_fin128<<<(int)(((size_t)E_EDGES * 128 + 255) / 256), 256>>>(sij, c2_b);

    // generator MLP: t4 = relu([xij|gemb]@g_w1+b1) (bf16 out), xl = relu(t4@g_w2+b2)
    mma_gemm<<<dim3(4, E_EDGES / 128), 256, MMA_SMEM_DYN>>>(
        cat1h, cat1l, 384, 384, wth + OFF_G1, wtl + OFF_G1, gb1,
        nullptr, t4h, t4l, 512, 1, 1);
    mma_gemm<<<dim3(1, E_EDGES / 128), 256, MMA_SMEM_DYN>>>(
        t4h, t4l, 512, 512, wth + OFF_G2, wtl + OFF_G2, gb2,
        xl, nullptr, nullptr, 128, 1, 0);
    k_mix<<<(int)(((size_t)E_EDGES * 128 + 255) / 256), 256>>>(gemb, attn);

    // classifier
    mma_gemm<<<dim3(1, E_EDGES / 128), 256, MMA_SMEM_DYN>>>(
        cat2h, cat2l, 256, 256, wth + OFF_CL, wtl + OFF_CL, cl_b1,
        sc, nullptr, nullptr, 128, 1, 0);
    k_out<<<(E_EDGES * 32 + 255) / 256, 256>>>(cl_w2, cl_b2, out);
}